// round 1
// baseline (speedup 1.0000x reference)
#include <cuda_runtime.h>
#include <cstdint>

// JAX threefry mode: 1 = partitionable (default in modern JAX), 0 = legacy counter split.
#define PARTITIONABLE 1

#define NN 8192
#define DD 64
#define EE 16384
#define NEGV -1e10f
#define TINYF 1.17549435e-38f

// ---------------- scratch (static device globals; no allocation) ----------------
__device__ float g_queries[NN * DD];
__device__ float g_qn[NN];
__device__ float g_hn[NN];
__device__ int   g_gens0[NN];
__device__ int   g_sel[NN];
__device__ int   g_gensF[NN];
__device__ int   g_newsend[NN];
__device__ int   g_newrec[NN];
__device__ int   g_ngens;
__device__ int   g_eactive;

// ---------------- threefry2x32 (JAX-exact, 20 rounds) ----------------
__host__ __device__ __forceinline__ void threefry2x32(uint32_t k0, uint32_t k1,
                                                      uint32_t x0, uint32_t x1,
                                                      uint32_t* o0, uint32_t* o1) {
  uint32_t ks2 = k0 ^ k1 ^ 0x1BD11BDAu;
#define ROTL32(v, r) (((v) << (r)) | ((v) >> (32 - (r))))
#define TFRND(r) { x0 += x1; x1 = ROTL32(x1, r); x1 ^= x0; }
  x0 += k0; x1 += k1;
  TFRND(13) TFRND(15) TFRND(26) TFRND(6)
  x0 += k1; x1 += ks2 + 1u;
  TFRND(17) TFRND(29) TFRND(16) TFRND(24)
  x0 += ks2; x1 += k0 + 2u;
  TFRND(13) TFRND(15) TFRND(26) TFRND(6)
  x0 += k0; x1 += k1 + 3u;
  TFRND(17) TFRND(29) TFRND(16) TFRND(24)
  x0 += k1; x1 += ks2 + 4u;
  TFRND(13) TFRND(15) TFRND(26) TFRND(6)
  x0 += ks2; x1 += k0 + 5u;
  *o0 = x0; *o1 = x1;
#undef TFRND
#undef ROTL32
}

// 32-bit random bits for linear element idx of a stream of `total` elements.
__device__ __forceinline__ uint32_t random_bits32(uint32_t k0, uint32_t k1,
                                                  unsigned long long idx,
                                                  unsigned long long total) {
#if PARTITIONABLE
  uint32_t o0, o1;
  threefry2x32(k0, k1, (uint32_t)(idx >> 32), (uint32_t)idx, &o0, &o1);
  return o0 ^ o1;
#else
  unsigned long long H = total >> 1;  // all our sizes are even
  uint32_t o0, o1;
  if (idx < H) { threefry2x32(k0, k1, (uint32_t)idx, (uint32_t)(idx + H), &o0, &o1); return o0; }
  else         { threefry2x32(k0, k1, (uint32_t)(idx - H), (uint32_t)idx, &o0, &o1); return o1; }
#endif
}

__device__ __forceinline__ float u01_from_bits(uint32_t bits) {
  return __uint_as_float((bits >> 9) | 0x3f800000u) - 1.0f;
}

// XLA's ErfInv (Giles polynomial) — matches lax.erf_inv on f32.
__device__ __forceinline__ float xla_erfinv(float x) {
  float w = -log1pf(-x * x);
  float p;
  if (w < 5.f) {
    w -= 2.5f;
    p = 2.81022636e-08f;
    p = fmaf(p, w, 3.43273939e-07f);
    p = fmaf(p, w, -3.5233877e-06f);
    p = fmaf(p, w, -4.39150654e-06f);
    p = fmaf(p, w, 0.00021858087f);
    p = fmaf(p, w, -0.00125372503f);
    p = fmaf(p, w, -0.00417768164f);
    p = fmaf(p, w, 0.246640727f);
    p = fmaf(p, w, 1.50140941f);
  } else {
    w = sqrtf(w) - 3.f;
    p = -0.000200214257f;
    p = fmaf(p, w, 0.000100950558f);
    p = fmaf(p, w, 0.00134934322f);
    p = fmaf(p, w, -0.00367342844f);
    p = fmaf(p, w, 0.00573950773f);
    p = fmaf(p, w, -0.0076224613f);
    p = fmaf(p, w, 0.00943887047f);
    p = fmaf(p, w, 1.00167406f);
    p = fmaf(p, w, 2.83297682f);
  }
  return p * x;
}

// ---------------- Kernel A: queries, norms, Bernoulli generators ----------------
__global__ void k_prep(const float* __restrict__ nodes, const float* __restrict__ Wq,
                       const float* __restrict__ bq, const float* __restrict__ Wp,
                       const float* __restrict__ bp, const float* __restrict__ active_nodes,
                       uint32_t kp0, uint32_t kp1) {
  int i = blockIdx.x;
  int t = threadIdx.x;  // 64 threads
  __shared__ float sn[DD], r1[DD], r2[DD], r3[DD];
  sn[t] = nodes[i * DD + t];
  __syncthreads();
  float q = bq[t];
#pragma unroll
  for (int k = 0; k < DD; k++) q = fmaf(sn[k], Wq[k * DD + t], q);
  g_queries[i * DD + t] = q;
  r1[t] = q * q;
  r2[t] = sn[t] * sn[t];
  r3[t] = sn[t] * Wp[t];
  __syncthreads();
  for (int d = 32; d > 0; d >>= 1) {
    if (t < d) { r1[t] += r1[t + d]; r2[t] += r2[t + d]; r3[t] += r3[t + d]; }
    __syncthreads();
  }
  if (t == 0) {
    g_qn[i] = r1[0];
    g_hn[i] = r2[0];
    float z = r3[0] + bp[0];
    float prob = 0.5f * tanhf(0.5f * z) + 0.5f;  // XLA logistic
    uint32_t bits = random_bits32(kp0, kp1, (unsigned long long)i, (unsigned long long)NN);
    float u = u01_from_bits(bits);
    g_gens0[i] = (u < prob * active_nodes[i]) ? 1 : 0;
  }
}

// ------- Kernel B: per-generator categorical (Gumbel-argmax) + edge-exists check -------
__global__ void k_select(const float* __restrict__ nodes, const int* __restrict__ senders,
                         const int* __restrict__ receivers, uint32_t ks0, uint32_t ks1) {
  int i = blockIdx.x;
  int tid = threadIdx.x;  // 256 threads
  if (g_gens0[i] == 0) {
    if (tid == 0) { g_sel[i] = 0; g_gensF[i] = 0; }
    return;
  }
  __shared__ float qsh[DD];
  if (tid < DD) qsh[tid] = g_queries[i * DD + tid];
  __syncthreads();
  float qn = g_qn[i];
  float best = -3.4e38f;
  int bidx = 0x7FFFFFFF;
  for (int j = tid; j < NN; j += 256) {
    const float* nr = nodes + j * DD;
    float num = 0.f;
#pragma unroll
    for (int k = 0; k < DD; k++) num = fmaf(qsh[k], nr[k], num);
    float s = num / (sqrtf(qn * g_hn[j]) + 1e-8f);
    s = fminf(fmaxf(s, -10000.f), 10000.f);
    if (j == i) s = NEGV;
    unsigned long long lin = (unsigned long long)i * NN + (unsigned long long)j;
    uint32_t bits = random_bits32(ks0, ks1, lin, (unsigned long long)NN * NN);
    float u = fmaxf(TINYF, u01_from_bits(bits) + TINYF);  // uniform(tiny, 1)
    float g = -logf(-logf(u));                            // gumbel
    float v = s + g;
    if (v > best) { best = v; bidx = j; }  // strict > keeps first index within thread
  }
  __shared__ float bv[256];
  __shared__ int bj[256];
  bv[tid] = best; bj[tid] = bidx;
  __syncthreads();
  for (int d = 128; d > 0; d >>= 1) {
    if (tid < d) {
      float v2 = bv[tid + d]; int j2 = bj[tid + d];
      if (v2 > bv[tid] || (v2 == bv[tid] && j2 < bj[tid])) { bv[tid] = v2; bj[tid] = j2; }
    }
    __syncthreads();
  }
  __shared__ int s_sel;
  __shared__ int s_exist;
  if (tid == 0) { s_sel = bj[0]; s_exist = 0; }
  __syncthreads();
  int sel = s_sel;
  int found = 0;
  for (int e = tid; e < EE; e += 256)
    if (senders[e] == i && receivers[e] == sel) found = 1;
  if (found) s_exist = 1;  // benign race: all writers store 1
  __syncthreads();
  if (tid == 0) { g_sel[i] = sel; g_gensF[i] = s_exist ? 0 : 1; }
}

// ---------------- Kernel C: e_active sum, scan generators, compact ----------------
__global__ void k_compact(const float* __restrict__ active_edges) {
  const int tid = threadIdx.x;  // 1024 threads
  __shared__ float sred[1024];
  float s = 0.f;
  for (int e = tid; e < EE; e += 1024) s += active_edges[e];
  sred[tid] = s;
  __syncthreads();
  for (int d = 512; d > 0; d >>= 1) {
    if (tid < d) sred[tid] += sred[tid + d];
    __syncthreads();
  }
  __shared__ int s_ea;
  if (tid == 0) { s_ea = (int)sred[0]; g_eactive = s_ea; }
  __syncthreads();

  int flags[8];
  int cnt = 0;
#pragma unroll
  for (int r = 0; r < 8; r++) {
    int i = tid * 8 + r;
    flags[r] = g_gensF[i];
    cnt += flags[r];
  }
  __shared__ int ss[1024];
  ss[tid] = cnt;
  __syncthreads();
  for (int d = 1; d < 1024; d <<= 1) {
    int v = (tid >= d) ? ss[tid - d] : 0;
    __syncthreads();
    ss[tid] += v;
    __syncthreads();
  }
  int incl = ss[tid];
  int off = incl - cnt;
#pragma unroll
  for (int r = 0; r < 8; r++) {
    int i = tid * 8 + r;
    if (flags[r]) { g_newsend[off] = i; g_newrec[off] = g_sel[i]; off++; }
  }
  if (tid == 1023) {
    int total = incl;
    int allowed = EE - s_ea - 1;
    int n = total < 0 ? 0 : total;
    if (n > allowed) n = allowed;
    g_ngens = n;
  }
}

// ---------------- Kernel D: write all outputs ----------------
// Layout: [ new_edges (E*D f32) | nsend (E) | nrec (E) | naedges (E) ]
__global__ void k_out(const float* __restrict__ edges, const int* __restrict__ senders,
                      const int* __restrict__ receivers, float* __restrict__ out,
                      uint32_t ke0, uint32_t ke1, int out_size) {
  int idx = blockIdx.x * blockDim.x + threadIdx.x;
  if (idx >= out_size) return;
  int ngen = g_ngens;
  int ea = g_eactive;
  const int T1 = EE * DD;
  if (idx < T1) {
    float v = edges[idx];
    int e = idx >> 6;  // D = 64
    if (e >= ea && e < ea + ngen) {
      uint32_t bits = random_bits32(ke0, ke1, (unsigned long long)idx,
                                    (unsigned long long)T1);
      float u01 = u01_from_bits(bits);
      const float lo = -0.99999994f;                 // nextafter(-1, 0)
      float u = fmaxf(lo, fmaf(u01, 2.0f, lo));      // (1 - lo) rounds to 2.0f
      v += 1.41421356f * xla_erfinv(u);              // sqrt(2) * erfinv
    }
    out[idx] = v;
  } else if (idx < T1 + EE) {
    int j = idx - T1;
    float v;
    if (j < ea)             v = (float)senders[j];
    else if (j < ea + ngen) v = (float)g_newsend[j - ea];
    else                    v = (float)(NN - 1);
    out[idx] = v;
  } else if (idx < T1 + 2 * EE) {
    int j = idx - T1 - EE;
    float v;
    if (j < ea)             v = (float)receivers[j];
    else if (j < ea + ngen) v = (float)g_newrec[j - ea];
    else                    v = (float)(NN - 1);
    out[idx] = v;
  } else if (idx < T1 + 3 * EE) {
    int j = idx - T1 - 2 * EE;
    out[idx] = (j < ea + ngen) ? 1.0f : 0.0f;
  } else {
    out[idx] = 0.0f;
  }
}

// ---------------- host ----------------
extern "C" void kernel_launch(void* const* d_in, const int* in_sizes, int n_in,
                              void* d_out, int out_size) {
  const float* nodes        = (const float*)d_in[0];
  const float* edges        = (const float*)d_in[1];
  const int*   receivers    = (const int*)d_in[2];
  const int*   senders      = (const int*)d_in[3];
  const float* active_nodes = (const float*)d_in[4];
  const float* active_edges = (const float*)d_in[5];
  const float* Wq           = (const float*)d_in[6];
  const float* bq           = (const float*)d_in[7];
  const float* Wp           = (const float*)d_in[8];
  const float* bp           = (const float*)d_in[9];
  (void)in_sizes; (void)n_in;

  // key = jax.random.key(42) -> data (0, 42); split into 3 subkeys.
  const uint32_t K0 = 0u, K1 = 42u;
  uint32_t kp0, kp1, ke0, ke1, ks0, ks1;
#if PARTITIONABLE
  threefry2x32(K0, K1, 0u, 0u, &kp0, &kp1);  // key_prob
  threefry2x32(K0, K1, 0u, 1u, &ke0, &ke1);  // key_edges
  threefry2x32(K0, K1, 0u, 2u, &ks0, &ks1);  // key_samp
#else
  // legacy split: counts iota(6) -> halves [0,1,2] / [3,4,5]; pairs (0,3),(1,4),(2,5)
  uint32_t a0, a1, b0, b1, c0, c1;
  threefry2x32(K0, K1, 0u, 3u, &a0, &a1);
  threefry2x32(K0, K1, 1u, 4u, &b0, &b1);
  threefry2x32(K0, K1, 2u, 5u, &c0, &c1);
  kp0 = a0; kp1 = b0;   // out[0], out[1]
  ke0 = c0; ke1 = a1;   // out[2], out[3]
  ks0 = b1; ks1 = c1;   // out[4], out[5]
#endif

  k_prep<<<NN, DD>>>(nodes, Wq, bq, Wp, bp, active_nodes, kp0, kp1);
  k_select<<<NN, 256>>>(nodes, senders, receivers, ks0, ks1);
  k_compact<<<1, 1024>>>(active_edges);
  int blocks = (out_size + 255) / 256;
  k_out<<<blocks, 256>>>(edges, senders, receivers, (float*)d_out, ke0, ke1, out_size);
}

// round 2
// speedup vs baseline: 5.9780x; 5.9780x over previous
#include <cuda_runtime.h>
#include <cstdint>

#define NN 8192
#define DD 64
#define EE 16384
#define NEGV -1e10f
#define TINYF 1.17549435e-38f

#define SEL_BLOCKS 888
#define SEL_THREADS 128
#define TILE_J 128
#define NCHUNK (NN / TILE_J)   // 64

// ---------------- scratch ----------------
__device__ float g_queries[NN * DD];
__device__ float g_qn[NN];
__device__ float g_hn[NN];
__device__ int   g_gens0[NN];
__device__ int   g_glist[NN];
__device__ int   g_selc[NN];
__device__ int   g_flag[NN];
__device__ unsigned long long g_best[NN];
__device__ int   g_newsend[NN];
__device__ int   g_newrec[NN];
__device__ int   g_ngens;
__device__ int   g_eactive;
__device__ int   g_ncand;

// ---------------- threefry2x32 (JAX-exact) ----------------
__host__ __device__ __forceinline__ void threefry2x32(uint32_t k0, uint32_t k1,
                                                      uint32_t x0, uint32_t x1,
                                                      uint32_t* o0, uint32_t* o1) {
  uint32_t ks2 = k0 ^ k1 ^ 0x1BD11BDAu;
#define ROTL32(v, r) (((v) << (r)) | ((v) >> (32 - (r))))
#define TFRND(r) { x0 += x1; x1 = ROTL32(x1, r); x1 ^= x0; }
  x0 += k0; x1 += k1;
  TFRND(13) TFRND(15) TFRND(26) TFRND(6)
  x0 += k1; x1 += ks2 + 1u;
  TFRND(17) TFRND(29) TFRND(16) TFRND(24)
  x0 += ks2; x1 += k0 + 2u;
  TFRND(13) TFRND(15) TFRND(26) TFRND(6)
  x0 += k0; x1 += k1 + 3u;
  TFRND(17) TFRND(29) TFRND(16) TFRND(24)
  x0 += k1; x1 += ks2 + 4u;
  TFRND(13) TFRND(15) TFRND(26) TFRND(6)
  x0 += ks2; x1 += k0 + 5u;
  *o0 = x0; *o1 = x1;
#undef TFRND
#undef ROTL32
}

__device__ __forceinline__ uint32_t random_bits32(uint32_t k0, uint32_t k1,
                                                  unsigned long long idx) {
  uint32_t o0, o1;
  threefry2x32(k0, k1, (uint32_t)(idx >> 32), (uint32_t)idx, &o0, &o1);
  return o0 ^ o1;
}

__device__ __forceinline__ float u01_from_bits(uint32_t bits) {
  return __uint_as_float((bits >> 9) | 0x3f800000u) - 1.0f;
}

// XLA ErfInv (Giles)
__device__ __forceinline__ float xla_erfinv(float x) {
  float w = -log1pf(-x * x);
  float p;
  if (w < 5.f) {
    w -= 2.5f;
    p = 2.81022636e-08f;
    p = fmaf(p, w, 3.43273939e-07f);
    p = fmaf(p, w, -3.5233877e-06f);
    p = fmaf(p, w, -4.39150654e-06f);
    p = fmaf(p, w, 0.00021858087f);
    p = fmaf(p, w, -0.00125372503f);
    p = fmaf(p, w, -0.00417768164f);
    p = fmaf(p, w, 0.246640727f);
    p = fmaf(p, w, 1.50140941f);
  } else {
    w = sqrtf(w) - 3.f;
    p = -0.000200214257f;
    p = fmaf(p, w, 0.000100950558f);
    p = fmaf(p, w, 0.00134934322f);
    p = fmaf(p, w, -0.00367342844f);
    p = fmaf(p, w, 0.00573950773f);
    p = fmaf(p, w, -0.0076224613f);
    p = fmaf(p, w, 0.00943887047f);
    p = fmaf(p, w, 1.00167406f);
    p = fmaf(p, w, 2.83297682f);
  }
  return p * x;
}

// monotone (value, smallest-j-wins) encoding for 64-bit atomicMax
__device__ __forceinline__ unsigned long long enc_key(float v, int j) {
  uint32_t u = __float_as_uint(v);
  u = (u & 0x80000000u) ? ~u : (u | 0x80000000u);
  return ((unsigned long long)u << 32) | (unsigned long long)(0xFFFFFFFFu - (uint32_t)j);
}

// ---------------- Kernel A: warp-per-node prep ----------------
__global__ void k_prep(const float* __restrict__ nodes, const float* __restrict__ Wq,
                       const float* __restrict__ bq, const float* __restrict__ Wp,
                       const float* __restrict__ bp, const float* __restrict__ active_nodes,
                       uint32_t kp0, uint32_t kp1) {
  int warp = threadIdx.x >> 5, lane = threadIdx.x & 31;
  int i = (blockIdx.x << 3) + warp;
  float2 n2 = reinterpret_cast<const float2*>(nodes + i * DD)[lane];
  float2 b2 = reinterpret_cast<const float2*>(bq)[lane];
  float q0 = b2.x, q1 = b2.y;
#pragma unroll
  for (int k = 0; k < DD; k++) {
    float nk = __shfl_sync(0xffffffffu, (k & 1) ? n2.y : n2.x, k >> 1);
    float2 w = reinterpret_cast<const float2*>(Wq + k * DD)[lane];
    q0 = fmaf(nk, w.x, q0);
    q1 = fmaf(nk, w.y, q1);
  }
  reinterpret_cast<float2*>(g_queries + i * DD)[lane] = make_float2(q0, q1);
  float2 wp2 = reinterpret_cast<const float2*>(Wp)[lane];
  float rq = q0 * q0 + q1 * q1;
  float rh = n2.x * n2.x + n2.y * n2.y;
  float rp = n2.x * wp2.x + n2.y * wp2.y;
#pragma unroll
  for (int d = 16; d > 0; d >>= 1) {
    rq += __shfl_xor_sync(0xffffffffu, rq, d);
    rh += __shfl_xor_sync(0xffffffffu, rh, d);
    rp += __shfl_xor_sync(0xffffffffu, rp, d);
  }
  if (lane == 0) {
    g_qn[i] = rq;
    g_hn[i] = rh;
    float z = rp + bp[0];
    float prob = 0.5f * tanhf(0.5f * z) + 0.5f;   // XLA logistic
    uint32_t bits = random_bits32(kp0, kp1, (unsigned long long)i);
    float u = u01_from_bits(bits);
    g_gens0[i] = (u < prob * active_nodes[i]) ? 1 : 0;
    g_best[i] = 0ull;
    g_flag[i] = 0;
  }
}

// ---------- Kernel B: e_active sum + ordered compaction of generators ----------
__global__ void k_listgen(const float* __restrict__ active_edges) {
  const int tid = threadIdx.x;  // 1024
  __shared__ float sred[1024];
  float s = 0.f;
  for (int e = tid; e < EE; e += 1024) s += active_edges[e];
  sred[tid] = s;
  __syncthreads();
  for (int d = 512; d > 0; d >>= 1) {
    if (tid < d) sred[tid] += sred[tid + d];
    __syncthreads();
  }
  if (tid == 0) g_eactive = (int)sred[0];

  int flags[8];
  int cnt = 0;
#pragma unroll
  for (int r = 0; r < 8; r++) {
    flags[r] = g_gens0[tid * 8 + r];
    cnt += flags[r];
  }
  __shared__ int ss[1024];
  ss[tid] = cnt;
  __syncthreads();
  for (int d = 1; d < 1024; d <<= 1) {
    int v = (tid >= d) ? ss[tid - d] : 0;
    __syncthreads();
    ss[tid] += v;
    __syncthreads();
  }
  int off = ss[tid] - cnt;
#pragma unroll
  for (int r = 0; r < 8; r++) {
    if (flags[r]) g_glist[off++] = tid * 8 + r;
  }
  if (tid == 1023) g_ncand = ss[1023];
}

// ---------- Kernel C: persistent tiled scoring + gumbel + atomic argmax ----------
__global__ void __launch_bounds__(SEL_THREADS) k_select(const float* __restrict__ nodes,
                                                        const float* __restrict__ active_nodes,
                                                        uint32_t ks0, uint32_t ks1) {
  __shared__ float sh[TILE_J * 65];
  __shared__ float qsh[DD];
  __shared__ float s_qn[1];
  __shared__ unsigned long long red[SEL_THREADS];
  const int tid = threadIdx.x;
  const int total = g_ncand * NCHUNK;
  for (int w = blockIdx.x; w < total; w += gridDim.x) {
    int c = w >> 6;           // NCHUNK = 64
    int chunk = w & 63;
    int i = g_glist[c];
    int jbase = chunk << 7;   // TILE_J = 128
    if (tid < DD) qsh[tid] = g_queries[i * DD + tid];
    if (tid == DD) s_qn[0] = g_qn[i];
    // coalesced tile load: 128 rows x 64 floats, padded stride 65
#pragma unroll
    for (int s = 0; s < 64; s++) {
      int f = (s << 7) | tid;
      sh[(f >> 6) * 65 + (f & 63)] = nodes[(jbase << 6) + f];
    }
    __syncthreads();
    int j = jbase + tid;
    float num = 0.f;
#pragma unroll
    for (int k = 0; k < DD; k++) num = fmaf(qsh[k], sh[tid * 65 + k], num);
    float sc = num / (sqrtf(s_qn[0] * g_hn[j]) + 1e-8f);
    sc = fminf(fmaxf(sc, -10000.f), 10000.f);
    if (active_nodes[j] <= 0.f) sc = NEGV;
    if (j == i) sc = NEGV;
    unsigned long long lin = (unsigned long long)i * NN + (unsigned long long)j;
    uint32_t bits = random_bits32(ks0, ks1, lin);
    float u = fmaxf(TINYF, u01_from_bits(bits) + TINYF);
    float g = -logf(-logf(u));
    unsigned long long key = enc_key(sc + g, j);
    red[tid] = key;
    __syncthreads();
#pragma unroll
    for (int d = SEL_THREADS / 2; d > 0; d >>= 1) {
      if (tid < d) { if (red[tid + d] > red[tid]) red[tid] = red[tid + d]; }
      __syncthreads();
    }
    if (tid == 0) atomicMax(&g_best[i], red[0]);
    // red[0] read precedes tid0's arrival at next iteration's barrier -> safe
  }
}

// ---------- Kernel D: existing-edge check per candidate ----------
__global__ void k_exist(const int* __restrict__ senders, const int* __restrict__ receivers) {
  const int tid = threadIdx.x;  // 256
  __shared__ int s_found;
  const int ncand = g_ncand;
  for (int c = blockIdx.x; c < ncand; c += gridDim.x) {
    int i = g_glist[c];
    int sel = (int)(0xFFFFFFFFu - (uint32_t)(g_best[i] & 0xFFFFFFFFull));
    if (tid == 0) s_found = 0;
    __syncthreads();
    int f = 0;
    for (int e = tid; e < EE; e += 256)
      f |= (senders[e] == i && receivers[e] == sel);
    if (f) s_found = 1;
    __syncthreads();
    if (tid == 0) { g_selc[c] = sel; g_flag[c] = s_found ? 0 : 1; }
    __syncthreads();
  }
}

// ---------- Kernel E: final ordered compaction ----------
__global__ void k_compact() {
  const int tid = threadIdx.x;  // 1024
  int flags[8];
  int cnt = 0;
#pragma unroll
  for (int r = 0; r < 8; r++) {
    flags[r] = g_flag[tid * 8 + r];
    cnt += flags[r];
  }
  __shared__ int ss[1024];
  ss[tid] = cnt;
  __syncthreads();
  for (int d = 1; d < 1024; d <<= 1) {
    int v = (tid >= d) ? ss[tid - d] : 0;
    __syncthreads();
    ss[tid] += v;
    __syncthreads();
  }
  int off = ss[tid] - cnt;
#pragma unroll
  for (int r = 0; r < 8; r++) {
    int c = tid * 8 + r;
    if (flags[r]) { g_newsend[off] = g_glist[c]; g_newrec[off] = g_selc[c]; off++; }
  }
  if (tid == 1023) {
    int total = ss[1023];
    int allowed = EE - g_eactive - 1;
    int n = total < 0 ? 0 : total;
    if (n > allowed) n = allowed;
    g_ngens = n;
  }
}

// ---------- Kernel F: vectorized output writer ----------
// Layout: [ new_edges (E*D f32) | nsend (E) | nrec (E) | naedges (E) ]
__global__ void k_out4(const float* __restrict__ edges, const int* __restrict__ senders,
                       const int* __restrict__ receivers, float4* __restrict__ out,
                       uint32_t ke0, uint32_t ke1, int n4) {
  int idx4 = blockIdx.x * blockDim.x + threadIdx.x;
  if (idx4 >= n4) return;
  int base = idx4 << 2;
  const int ngen = g_ngens;
  const int ea = g_eactive;
  const int T1 = EE * DD;
  float4 v;
  if (base < T1) {
    v = reinterpret_cast<const float4*>(edges)[idx4];
    int e = base >> 6;
    if (e >= ea && e < ea + ngen) {
      float* vp = reinterpret_cast<float*>(&v);
#pragma unroll
      for (int cmp = 0; cmp < 4; cmp++) {
        uint32_t bits = random_bits32(ke0, ke1, (unsigned long long)(base + cmp));
        float u01 = u01_from_bits(bits);
        const float lo = -0.99999994f;
        float u = fmaxf(lo, fmaf(u01, 2.0f, lo));
        vp[cmp] += 1.41421356f * xla_erfinv(u);
      }
    }
  } else if (base < T1 + EE) {
    float* vp = reinterpret_cast<float*>(&v);
#pragma unroll
    for (int cmp = 0; cmp < 4; cmp++) {
      int j = base + cmp - T1;
      float x;
      if (j < ea)             x = (float)senders[j];
      else if (j < ea + ngen) x = (float)g_newsend[j - ea];
      else                    x = (float)(NN - 1);
      vp[cmp] = x;
    }
  } else if (base < T1 + 2 * EE) {
    float* vp = reinterpret_cast<float*>(&v);
#pragma unroll
    for (int cmp = 0; cmp < 4; cmp++) {
      int j = base + cmp - T1 - EE;
      float x;
      if (j < ea)             x = (float)receivers[j];
      else if (j < ea + ngen) x = (float)g_newrec[j - ea];
      else                    x = (float)(NN - 1);
      vp[cmp] = x;
    }
  } else {
    float* vp = reinterpret_cast<float*>(&v);
#pragma unroll
    for (int cmp = 0; cmp < 4; cmp++) {
      int j = base + cmp - T1 - 2 * EE;
      vp[cmp] = (j < ea + ngen) ? 1.0f : 0.0f;
    }
  }
  out[idx4] = v;
}

// fallback scalar writer for non-multiple-of-4 sizes (not expected)
__global__ void k_out1(const float* __restrict__ edges, const int* __restrict__ senders,
                       const int* __restrict__ receivers, float* __restrict__ out,
                       uint32_t ke0, uint32_t ke1, int start, int out_size) {
  int idx = start + blockIdx.x * blockDim.x + threadIdx.x;
  if (idx >= out_size) return;
  const int ngen = g_ngens;
  const int ea = g_eactive;
  const int T1 = EE * DD;
  float x = 0.f;
  if (idx < T1) {
    x = edges[idx];
    int e = idx >> 6;
    if (e >= ea && e < ea + ngen) {
      uint32_t bits = random_bits32(ke0, ke1, (unsigned long long)idx);
      float u01 = u01_from_bits(bits);
      const float lo = -0.99999994f;
      float u = fmaxf(lo, fmaf(u01, 2.0f, lo));
      x += 1.41421356f * xla_erfinv(u);
    }
  } else if (idx < T1 + EE) {
    int j = idx - T1;
    if (j < ea)             x = (float)senders[j];
    else if (j < ea + ngen) x = (float)g_newsend[j - ea];
    else                    x = (float)(NN - 1);
  } else if (idx < T1 + 2 * EE) {
    int j = idx - T1 - EE;
    if (j < ea)             x = (float)receivers[j];
    else if (j < ea + ngen) x = (float)g_newrec[j - ea];
    else                    x = (float)(NN - 1);
  } else if (idx < T1 + 3 * EE) {
    int j = idx - T1 - 2 * EE;
    x = (j < ea + ngen) ? 1.0f : 0.0f;
  }
  out[idx] = x;
}

// ---------------- host ----------------
extern "C" void kernel_launch(void* const* d_in, const int* in_sizes, int n_in,
                              void* d_out, int out_size) {
  const float* nodes        = (const float*)d_in[0];
  const float* edges        = (const float*)d_in[1];
  const int*   receivers    = (const int*)d_in[2];
  const int*   senders      = (const int*)d_in[3];
  const float* active_nodes = (const float*)d_in[4];
  const float* active_edges = (const float*)d_in[5];
  const float* Wq           = (const float*)d_in[6];
  const float* bq           = (const float*)d_in[7];
  const float* Wp           = (const float*)d_in[8];
  const float* bp           = (const float*)d_in[9];
  (void)in_sizes; (void)n_in;

  const uint32_t K0 = 0u, K1 = 42u;
  uint32_t kp0, kp1, ke0, ke1, ks0, ks1;
  threefry2x32(K0, K1, 0u, 0u, &kp0, &kp1);  // key_prob
  threefry2x32(K0, K1, 0u, 1u, &ke0, &ke1);  // key_edges
  threefry2x32(K0, K1, 0u, 2u, &ks0, &ks1);  // key_samp

  k_prep<<<NN / 8, 256>>>(nodes, Wq, bq, Wp, bp, active_nodes, kp0, kp1);
  k_listgen<<<1, 1024>>>(active_edges);
  k_select<<<SEL_BLOCKS, SEL_THREADS>>>(nodes, active_nodes, ks0, ks1);
  k_exist<<<296, 256>>>(senders, receivers);
  k_compact<<<1, 1024>>>();

  int n4 = out_size >> 2;
  if (n4 > 0)
    k_out4<<<(n4 + 255) / 256, 256>>>(edges, senders, receivers, (float4*)d_out,
                                      ke0, ke1, n4);
  int rem_start = n4 << 2;
  if (rem_start < out_size)
    k_out1<<<1, 256>>>(edges, senders, receivers, (float*)d_out, ke0, ke1,
                       rem_start, out_size);
}

// round 3
// speedup vs baseline: 9.1122x; 1.5243x over previous
#include <cuda_runtime.h>
#include <cstdint>

#define NN 8192
#define DD 64
#define EE 16384
#define NEGV -1e10f
#define TINYF 1.17549435e-38f

#define SEL_THREADS 128
#define TILE_J 128
#define NCHUNK (NN / TILE_J)   // 64
#define CAND_TILE 32

// ---------------- scratch ----------------
__device__ float g_queries[NN * DD];
__device__ float g_qn[NN];
__device__ float g_hn[NN];
__device__ int   g_gens0[NN];
__device__ int   g_glist[NN];
__device__ int   g_flag[NN];
__device__ unsigned long long g_best[NN];
__device__ int   g_newsend[NN];
__device__ int   g_newrec[NN];
__device__ int   g_ngens;
__device__ int   g_eactive;
__device__ int   g_ncand;

// ---------------- threefry2x32 (JAX-exact) ----------------
__host__ __device__ __forceinline__ void threefry2x32(uint32_t k0, uint32_t k1,
                                                      uint32_t x0, uint32_t x1,
                                                      uint32_t* o0, uint32_t* o1) {
  uint32_t ks2 = k0 ^ k1 ^ 0x1BD11BDAu;
#define ROTL32(v, r) (((v) << (r)) | ((v) >> (32 - (r))))
#define TFRND(r) { x0 += x1; x1 = ROTL32(x1, r); x1 ^= x0; }
  x0 += k0; x1 += k1;
  TFRND(13) TFRND(15) TFRND(26) TFRND(6)
  x0 += k1; x1 += ks2 + 1u;
  TFRND(17) TFRND(29) TFRND(16) TFRND(24)
  x0 += ks2; x1 += k0 + 2u;
  TFRND(13) TFRND(15) TFRND(26) TFRND(6)
  x0 += k0; x1 += k1 + 3u;
  TFRND(17) TFRND(29) TFRND(16) TFRND(24)
  x0 += k1; x1 += ks2 + 4u;
  TFRND(13) TFRND(15) TFRND(26) TFRND(6)
  x0 += ks2; x1 += k0 + 5u;
  *o0 = x0; *o1 = x1;
#undef TFRND
#undef ROTL32
}

__device__ __forceinline__ uint32_t random_bits32(uint32_t k0, uint32_t k1,
                                                  unsigned long long idx) {
  uint32_t o0, o1;
  threefry2x32(k0, k1, (uint32_t)(idx >> 32), (uint32_t)idx, &o0, &o1);
  return o0 ^ o1;
}

__device__ __forceinline__ float u01_from_bits(uint32_t bits) {
  return __uint_as_float((bits >> 9) | 0x3f800000u) - 1.0f;
}

// XLA ErfInv (Giles)
__device__ __forceinline__ float xla_erfinv(float x) {
  float w = -log1pf(-x * x);
  float p;
  if (w < 5.f) {
    w -= 2.5f;
    p = 2.81022636e-08f;
    p = fmaf(p, w, 3.43273939e-07f);
    p = fmaf(p, w, -3.5233877e-06f);
    p = fmaf(p, w, -4.39150654e-06f);
    p = fmaf(p, w, 0.00021858087f);
    p = fmaf(p, w, -0.00125372503f);
    p = fmaf(p, w, -0.00417768164f);
    p = fmaf(p, w, 0.246640727f);
    p = fmaf(p, w, 1.50140941f);
  } else {
    w = sqrtf(w) - 3.f;
    p = -0.000200214257f;
    p = fmaf(p, w, 0.000100950558f);
    p = fmaf(p, w, 0.00134934322f);
    p = fmaf(p, w, -0.00367342844f);
    p = fmaf(p, w, 0.00573950773f);
    p = fmaf(p, w, -0.0076224613f);
    p = fmaf(p, w, 0.00943887047f);
    p = fmaf(p, w, 1.00167406f);
    p = fmaf(p, w, 2.83297682f);
  }
  return p * x;
}

// monotone (value, smallest-j-wins) encoding for 64-bit atomicMax
__device__ __forceinline__ unsigned long long enc_key(float v, int j) {
  uint32_t u = __float_as_uint(v);
  u = (u & 0x80000000u) ? ~u : (u | 0x80000000u);
  return ((unsigned long long)u << 32) | (unsigned long long)(0xFFFFFFFFu - (uint32_t)j);
}

__device__ __forceinline__ int warp_incl_scan(int v, int lane) {
#pragma unroll
  for (int d = 1; d < 32; d <<= 1) {
    int o = __shfl_up_sync(0xffffffffu, v, d);
    if (lane >= d) v += o;
  }
  return v;
}

// ---------------- Kernel A: warp-per-node prep ----------------
__global__ void k_prep(const float* __restrict__ nodes, const float* __restrict__ Wq,
                       const float* __restrict__ bq, const float* __restrict__ Wp,
                       const float* __restrict__ bp, const float* __restrict__ active_nodes,
                       uint32_t kp0, uint32_t kp1) {
  int warp = threadIdx.x >> 5, lane = threadIdx.x & 31;
  int i = (blockIdx.x << 3) + warp;
  float2 n2 = reinterpret_cast<const float2*>(nodes + i * DD)[lane];
  float2 b2 = reinterpret_cast<const float2*>(bq)[lane];
  float q0 = b2.x, q1 = b2.y;
#pragma unroll
  for (int k = 0; k < DD; k++) {
    float nk = __shfl_sync(0xffffffffu, (k & 1) ? n2.y : n2.x, k >> 1);
    float2 w = reinterpret_cast<const float2*>(Wq + k * DD)[lane];
    q0 = fmaf(nk, w.x, q0);
    q1 = fmaf(nk, w.y, q1);
  }
  reinterpret_cast<float2*>(g_queries + i * DD)[lane] = make_float2(q0, q1);
  float2 wp2 = reinterpret_cast<const float2*>(Wp)[lane];
  float rq = q0 * q0 + q1 * q1;
  float rh = n2.x * n2.x + n2.y * n2.y;
  float rp = n2.x * wp2.x + n2.y * wp2.y;
#pragma unroll
  for (int d = 16; d > 0; d >>= 1) {
    rq += __shfl_xor_sync(0xffffffffu, rq, d);
    rh += __shfl_xor_sync(0xffffffffu, rh, d);
    rp += __shfl_xor_sync(0xffffffffu, rp, d);
  }
  if (lane == 0) {
    g_qn[i] = rq;
    g_hn[i] = rh;
    float z = rp + bp[0];
    float prob = 0.5f * tanhf(0.5f * z) + 0.5f;   // XLA logistic
    uint32_t bits = random_bits32(kp0, kp1, (unsigned long long)i);
    float u = u01_from_bits(bits);
    g_gens0[i] = (u < prob * active_nodes[i]) ? 1 : 0;
    g_best[i] = 0ull;
  }
}

// ---------- Kernel B: e_active sum + ordered compaction of generators ----------
__global__ void k_listgen(const float* __restrict__ active_edges) {
  const int tid = threadIdx.x;  // 1024
  const int lane = tid & 31, wid = tid >> 5;
  __shared__ float wsumf[32];
  __shared__ int wsum[32];
  __shared__ int wpre[33];

  // e_active reduction (float4, warp shuffles)
  const float4* ae4 = reinterpret_cast<const float4*>(active_edges);
  float s = 0.f;
#pragma unroll
  for (int r = 0; r < 4; r++) {
    float4 v = ae4[tid + (r << 10)];
    s += v.x + v.y + v.z + v.w;
  }
#pragma unroll
  for (int d = 16; d > 0; d >>= 1) s += __shfl_xor_sync(0xffffffffu, s, d);
  if (lane == 0) wsumf[wid] = s;

  // generator flags + counts
  int flags[8];
  int cnt = 0;
#pragma unroll
  for (int r = 0; r < 8; r++) {
    flags[r] = g_gens0[tid * 8 + r];
    cnt += flags[r];
  }
  int incl = warp_incl_scan(cnt, lane);
  if (lane == 31) wsum[wid] = incl;
  __syncthreads();
  if (wid == 0) {
    int v = wsum[lane];
    int sc = warp_incl_scan(v, lane);
    wpre[lane + 1] = sc;
    if (lane == 0) {
      wpre[0] = 0;
      float t = 0.f;
#pragma unroll
      for (int w = 0; w < 32; w++) t += wsumf[w];
      g_eactive = (int)t;
    }
  }
  __syncthreads();
  int off = wpre[wid] + incl - cnt;
#pragma unroll
  for (int r = 0; r < 8; r++) {
    if (flags[r]) {
      g_glist[off] = tid * 8 + r;
      g_flag[off] = 1;
      off++;
    }
  }
  if (tid == 1023) g_ncand = wpre[32];
}

// ---------- Kernel C: persistent chunk x cand-group scoring ----------
__global__ void __launch_bounds__(SEL_THREADS) k_select(const float* __restrict__ nodes,
                                                        const float* __restrict__ active_nodes,
                                                        uint32_t ks0, uint32_t ks1) {
  __shared__ float sh[TILE_J * 66];         // padded stride 66 floats (f2-vectorizable)
  __shared__ float qsh[CAND_TILE * DD];
  __shared__ float s_qn[CAND_TILE];
  __shared__ int   s_ii[CAND_TILE];
  const int tid = threadIdx.x;
  const int lane = tid & 31;
  const int ncand = g_ncand;
  const int ng = (ncand + CAND_TILE - 1) / CAND_TILE;
  const int total = NCHUNK * ng;
  for (int w = blockIdx.x; w < total; w += gridDim.x) {
    const int chunk = w / ng;
    const int grp = w - chunk * ng;
    const int c0 = grp * CAND_TILE;
    const int jbase = chunk << 7;
    // tile load: 128 rows x 64 floats, coalesced
#pragma unroll
    for (int s = 0; s < 64; s++) {
      int f = (s << 7) | tid;
      sh[(f >> 6) * 66 + (f & 63)] = nodes[(jbase << 6) + f];
    }
    // candidate queries / norms
    if (tid < CAND_TILE) {
      int idx = c0 + tid;
      int i = (idx < ncand) ? g_glist[idx] : 0;
      s_ii[tid] = i;
      s_qn[tid] = g_qn[i];
    }
    for (int t = tid; t < CAND_TILE * DD; t += SEL_THREADS) {
      int c = t >> 6, k = t & 63;
      int idx = c0 + c;
      qsh[t] = (idx < ncand) ? g_queries[g_glist[idx] * DD + k] : 0.f;
    }
    __syncthreads();
    const int j = jbase + tid;
    const float hn = g_hn[j];
    const float act = active_nodes[j];
    const float2* rowf2 = reinterpret_cast<const float2*>(sh) + tid * 33;
    const int cmax = (ncand - c0 < CAND_TILE) ? (ncand - c0) : CAND_TILE;
    for (int c = 0; c < cmax; c++) {
      const int i = s_ii[c];
      const float2* qf2 = reinterpret_cast<const float2*>(qsh) + c * 32;
      float a0 = 0.f, a1 = 0.f;
#pragma unroll
      for (int kk = 0; kk < 32; kk++) {
        float2 r = rowf2[kk];
        float2 q = qf2[kk];
        a0 = fmaf(q.x, r.x, a0);
        a1 = fmaf(q.y, r.y, a1);
      }
      float num = a0 + a1;
      float sc = num / (sqrtf(s_qn[c] * hn) + 1e-8f);
      sc = fminf(fmaxf(sc, -10000.f), 10000.f);
      if (act <= 0.f) sc = NEGV;
      if (j == i) sc = NEGV;
      unsigned long long lin = (unsigned long long)i * NN + (unsigned long long)j;
      uint32_t bits = random_bits32(ks0, ks1, lin);
      float u = fmaxf(TINYF, u01_from_bits(bits) + TINYF);
      float g = -logf(-logf(u));
      unsigned long long key = enc_key(sc + g, j);
#pragma unroll
      for (int d = 16; d > 0; d >>= 1) {
        unsigned long long o = __shfl_xor_sync(0xffffffffu, key, d);
        if (o > key) key = o;
      }
      if (lane == 0) atomicMax(&g_best[i], key);
    }
    __syncthreads();
  }
}

// ---------- Kernel D: edge-parallel existing-edge check ----------
__global__ void k_exist(const int* __restrict__ senders, const int* __restrict__ receivers) {
  __shared__ unsigned long long keys[2048];
  const int tid = threadIdx.x;  // 256
  const int ncand = g_ncand;
  const int e = (blockIdx.x << 8) + tid;
  const unsigned long long ekey =
      ((unsigned long long)(uint32_t)senders[e] << 32) | (uint32_t)receivers[e];
  for (int base = 0; base < ncand; base += 2048) {
    int m = ncand - base;
    if (m > 2048) m = 2048;
    for (int t = tid; t < m; t += 256) {
      int i = g_glist[base + t];
      unsigned long long b = g_best[i];
      uint32_t sel = 0xFFFFFFFFu - (uint32_t)(b & 0xFFFFFFFFull);
      keys[t] = ((unsigned long long)(uint32_t)i << 32) | sel;
    }
    __syncthreads();
    for (int k = 0; k < m; k++) {
      if (ekey == keys[k]) g_flag[base + k] = 0;
    }
    __syncthreads();
  }
}

// ---------- Kernel E: final ordered compaction (warp scans) ----------
__global__ void k_compact() {
  const int tid = threadIdx.x;  // 1024
  const int lane = tid & 31, wid = tid >> 5;
  __shared__ int wsum[32];
  __shared__ int wpre[33];
  const int ncand = g_ncand;
  int flags[8];
  int cnt = 0;
#pragma unroll
  for (int r = 0; r < 8; r++) {
    int c = tid * 8 + r;
    flags[r] = (c < ncand) ? g_flag[c] : 0;
    cnt += flags[r];
  }
  int incl = warp_incl_scan(cnt, lane);
  if (lane == 31) wsum[wid] = incl;
  __syncthreads();
  if (wid == 0) {
    int v = wsum[lane];
    int sc = warp_incl_scan(v, lane);
    wpre[lane + 1] = sc;
    if (lane == 0) wpre[0] = 0;
  }
  __syncthreads();
  int off = wpre[wid] + incl - cnt;
#pragma unroll
  for (int r = 0; r < 8; r++) {
    int c = tid * 8 + r;
    if (flags[r]) {
      int i = g_glist[c];
      unsigned long long b = g_best[i];
      g_newsend[off] = i;
      g_newrec[off] = (int)(0xFFFFFFFFu - (uint32_t)(b & 0xFFFFFFFFull));
      off++;
    }
  }
  if (tid == 1023) {
    int total = wpre[32];
    int allowed = EE - g_eactive - 1;
    int n = total < 0 ? 0 : total;
    if (n > allowed) n = allowed;
    g_ngens = n;
  }
}

// ---------- Kernel F: vectorized output writer (MLP=4) ----------
// Layout: [ new_edges (E*D f32) | nsend (E) | nrec (E) | naedges (E) ]
__global__ void k_out4(const float* __restrict__ edges, const int* __restrict__ senders,
                       const int* __restrict__ receivers, float4* __restrict__ out,
                       uint32_t ke0, uint32_t ke1, int n4) {
  const int ngen = g_ngens;
  const int ea = g_eactive;
  const int T1 = EE * DD;
  const int base0 = blockIdx.x * (blockDim.x << 2) + threadIdx.x;
#pragma unroll
  for (int u = 0; u < 4; u++) {
    int idx4 = base0 + u * blockDim.x;
    if (idx4 >= n4) continue;
    int base = idx4 << 2;
    float4 v;
    if (base < T1) {
      v = reinterpret_cast<const float4*>(edges)[idx4];
      int e = base >> 6;
      if (e >= ea && e < ea + ngen) {
        float* vp = reinterpret_cast<float*>(&v);
#pragma unroll
        for (int cmp = 0; cmp < 4; cmp++) {
          uint32_t bits = random_bits32(ke0, ke1, (unsigned long long)(base + cmp));
          float u01 = u01_from_bits(bits);
          const float lo = -0.99999994f;
          float uu = fmaxf(lo, fmaf(u01, 2.0f, lo));
          vp[cmp] += 1.41421356f * xla_erfinv(uu);
        }
      }
    } else if (base < T1 + EE) {
      float* vp = reinterpret_cast<float*>(&v);
#pragma unroll
      for (int cmp = 0; cmp < 4; cmp++) {
        int j = base + cmp - T1;
        float x;
        if (j < ea)             x = (float)senders[j];
        else if (j < ea + ngen) x = (float)g_newsend[j - ea];
        else                    x = (float)(NN - 1);
        vp[cmp] = x;
      }
    } else if (base < T1 + 2 * EE) {
      float* vp = reinterpret_cast<float*>(&v);
#pragma unroll
      for (int cmp = 0; cmp < 4; cmp++) {
        int j = base + cmp - T1 - EE;
        float x;
        if (j < ea)             x = (float)receivers[j];
        else if (j < ea + ngen) x = (float)g_newrec[j - ea];
        else                    x = (float)(NN - 1);
        vp[cmp] = x;
      }
    } else {
      float* vp = reinterpret_cast<float*>(&v);
#pragma unroll
      for (int cmp = 0; cmp < 4; cmp++) {
        int j = base + cmp - T1 - 2 * EE;
        vp[cmp] = (j < ea + ngen) ? 1.0f : 0.0f;
      }
    }
    out[idx4] = v;
  }
}

// fallback scalar writer for non-multiple-of-4 sizes (not expected)
__global__ void k_out1(const float* __restrict__ edges, const int* __restrict__ senders,
                       const int* __restrict__ receivers, float* __restrict__ out,
                       uint32_t ke0, uint32_t ke1, int start, int out_size) {
  int idx = start + blockIdx.x * blockDim.x + threadIdx.x;
  if (idx >= out_size) return;
  const int ngen = g_ngens;
  const int ea = g_eactive;
  const int T1 = EE * DD;
  float x = 0.f;
  if (idx < T1) {
    x = edges[idx];
    int e = idx >> 6;
    if (e >= ea && e < ea + ngen) {
      uint32_t bits = random_bits32(ke0, ke1, (unsigned long long)idx);
      float u01 = u01_from_bits(bits);
      const float lo = -0.99999994f;
      float u = fmaxf(lo, fmaf(u01, 2.0f, lo));
      x += 1.41421356f * xla_erfinv(u);
    }
  } else if (idx < T1 + EE) {
    int j = idx - T1;
    if (j < ea)             x = (float)senders[j];
    else if (j < ea + ngen) x = (float)g_newsend[j - ea];
    else                    x = (float)(NN - 1);
  } else if (idx < T1 + 2 * EE) {
    int j = idx - T1 - EE;
    if (j < ea)             x = (float)receivers[j];
    else if (j < ea + ngen) x = (float)g_newrec[j - ea];
    else                    x = (float)(NN - 1);
  } else if (idx < T1 + 3 * EE) {
    int j = idx - T1 - 2 * EE;
    x = (j < ea + ngen) ? 1.0f : 0.0f;
  }
  out[idx] = x;
}

// ---------------- host ----------------
extern "C" void kernel_launch(void* const* d_in, const int* in_sizes, int n_in,
                              void* d_out, int out_size) {
  const float* nodes        = (const float*)d_in[0];
  const float* edges        = (const float*)d_in[1];
  const int*   receivers    = (const int*)d_in[2];
  const int*   senders      = (const int*)d_in[3];
  const float* active_nodes = (const float*)d_in[4];
  const float* active_edges = (const float*)d_in[5];
  const float* Wq           = (const float*)d_in[6];
  const float* bq           = (const float*)d_in[7];
  const float* Wp           = (const float*)d_in[8];
  const float* bp           = (const float*)d_in[9];
  (void)in_sizes; (void)n_in;

  const uint32_t K0 = 0u, K1 = 42u;
  uint32_t kp0, kp1, ke0, ke1, ks0, ks1;
  threefry2x32(K0, K1, 0u, 0u, &kp0, &kp1);  // key_prob
  threefry2x32(K0, K1, 0u, 1u, &ke0, &ke1);  // key_edges
  threefry2x32(K0, K1, 0u, 2u, &ks0, &ks1);  // key_samp

  k_prep<<<NN / 8, 256>>>(nodes, Wq, bq, Wp, bp, active_nodes, kp0, kp1);
  k_listgen<<<1, 1024>>>(active_edges);
  k_select<<<592, SEL_THREADS>>>(nodes, active_nodes, ks0, ks1);
  k_exist<<<EE / 256, 256>>>(senders, receivers);
  k_compact<<<1, 1024>>>();

  int n4 = out_size >> 2;
  if (n4 > 0) {
    int blocks = (n4 + 1023) / 1024;
    k_out4<<<blocks, 256>>>(edges, senders, receivers, (float4*)d_out, ke0, ke1, n4);
  }
  int rem_start = n4 << 2;
  if (rem_start < out_size)
    k_out1<<<1, 256>>>(edges, senders, receivers, (float*)d_out, ke0, ke1,
                       rem_start, out_size);
}

// round 4
// speedup vs baseline: 9.7472x; 1.0697x over previous
#include <cuda_runtime.h>
#include <cstdint>

#define NN 8192
#define DD 64
#define EE 16384
#define NEGV -1e10f
#define TINYF 1.17549435e-38f

#define SEL_THREADS 256
#define TILE_J 128
#define TILE_STRIDE 68          // floats; 272B rows -> 16B aligned, LDS.128 conflict-free
#define NCHUNK (NN / TILE_J)    // 64
#define CAND_TILE 32

// ---------------- scratch ----------------
__device__ float g_queries[NN * DD];
__device__ float g_qn[NN];
__device__ float g_hn[NN];
__device__ int   g_gens0[NN];
__device__ int   g_glist[NN];
__device__ int   g_flag[NN];
__device__ unsigned long long g_best[NN];
__device__ int   g_newsend[NN];
__device__ int   g_newrec[NN];
__device__ int   g_ngens;
__device__ int   g_eactive;
__device__ int   g_ncand;

// ---------------- threefry2x32 (JAX-exact) ----------------
__host__ __device__ __forceinline__ void threefry2x32(uint32_t k0, uint32_t k1,
                                                      uint32_t x0, uint32_t x1,
                                                      uint32_t* o0, uint32_t* o1) {
  uint32_t ks2 = k0 ^ k1 ^ 0x1BD11BDAu;
#define ROTL32(v, r) (((v) << (r)) | ((v) >> (32 - (r))))
#define TFRND(r) { x0 += x1; x1 = ROTL32(x1, r); x1 ^= x0; }
  x0 += k0; x1 += k1;
  TFRND(13) TFRND(15) TFRND(26) TFRND(6)
  x0 += k1; x1 += ks2 + 1u;
  TFRND(17) TFRND(29) TFRND(16) TFRND(24)
  x0 += ks2; x1 += k0 + 2u;
  TFRND(13) TFRND(15) TFRND(26) TFRND(6)
  x0 += k0; x1 += k1 + 3u;
  TFRND(17) TFRND(29) TFRND(16) TFRND(24)
  x0 += k1; x1 += ks2 + 4u;
  TFRND(13) TFRND(15) TFRND(26) TFRND(6)
  x0 += ks2; x1 += k0 + 5u;
  *o0 = x0; *o1 = x1;
#undef TFRND
#undef ROTL32
}

__device__ __forceinline__ uint32_t random_bits32(uint32_t k0, uint32_t k1,
                                                  unsigned long long idx) {
  uint32_t o0, o1;
  threefry2x32(k0, k1, (uint32_t)(idx >> 32), (uint32_t)idx, &o0, &o1);
  return o0 ^ o1;
}

__device__ __forceinline__ float u01_from_bits(uint32_t bits) {
  return __uint_as_float((bits >> 9) | 0x3f800000u) - 1.0f;
}

// XLA ErfInv (Giles)
__device__ __forceinline__ float xla_erfinv(float x) {
  float w = -log1pf(-x * x);
  float p;
  if (w < 5.f) {
    w -= 2.5f;
    p = 2.81022636e-08f;
    p = fmaf(p, w, 3.43273939e-07f);
    p = fmaf(p, w, -3.5233877e-06f);
    p = fmaf(p, w, -4.39150654e-06f);
    p = fmaf(p, w, 0.00021858087f);
    p = fmaf(p, w, -0.00125372503f);
    p = fmaf(p, w, -0.00417768164f);
    p = fmaf(p, w, 0.246640727f);
    p = fmaf(p, w, 1.50140941f);
  } else {
    w = sqrtf(w) - 3.f;
    p = -0.000200214257f;
    p = fmaf(p, w, 0.000100950558f);
    p = fmaf(p, w, 0.00134934322f);
    p = fmaf(p, w, -0.00367342844f);
    p = fmaf(p, w, 0.00573950773f);
    p = fmaf(p, w, -0.0076224613f);
    p = fmaf(p, w, 0.00943887047f);
    p = fmaf(p, w, 1.00167406f);
    p = fmaf(p, w, 2.83297682f);
  }
  return p * x;
}

// monotone (value, smallest-j-wins) encoding for 64-bit atomicMax
__device__ __forceinline__ unsigned long long enc_key(float v, int j) {
  uint32_t u = __float_as_uint(v);
  u = (u & 0x80000000u) ? ~u : (u | 0x80000000u);
  return ((unsigned long long)u << 32) | (unsigned long long)(0xFFFFFFFFu - (uint32_t)j);
}

__device__ __forceinline__ int warp_incl_scan(int v, int lane) {
#pragma unroll
  for (int d = 1; d < 32; d <<= 1) {
    int o = __shfl_up_sync(0xffffffffu, v, d);
    if (lane >= d) v += o;
  }
  return v;
}

// ---------------- Kernel A: warp-per-node prep, Wq staged in smem ----------------
__global__ void __launch_bounds__(512) k_prep(const float* __restrict__ nodes,
                                              const float* __restrict__ Wq,
                                              const float* __restrict__ bq,
                                              const float* __restrict__ Wp,
                                              const float* __restrict__ bp,
                                              const float* __restrict__ active_nodes,
                                              uint32_t kp0, uint32_t kp1) {
  __shared__ float sWq[DD * DD];
  __shared__ float sbq[DD];
  __shared__ float sWp[DD];
  const int tid = threadIdx.x;           // 512
  const int warp = tid >> 5, lane = tid & 31;
  // stage Wq (4096 floats), bq, Wp
  {
    const float4* w4 = reinterpret_cast<const float4*>(Wq);
    float4* s4 = reinterpret_cast<float4*>(sWq);
#pragma unroll
    for (int r = 0; r < 2; r++) s4[tid + (r << 9)] = w4[tid + (r << 9)];
    if (tid < DD) { sbq[tid] = bq[tid]; sWp[tid] = Wp[tid]; }
  }
  __syncthreads();
  const int i = (blockIdx.x << 4) + warp;
  float2 n2 = reinterpret_cast<const float2*>(nodes + i * DD)[lane];
  float2 b2 = reinterpret_cast<const float2*>(sbq)[lane];
  float q0 = b2.x, q1 = b2.y;
#pragma unroll
  for (int k = 0; k < DD; k++) {
    float nk = __shfl_sync(0xffffffffu, (k & 1) ? n2.y : n2.x, k >> 1);
    float2 w = reinterpret_cast<const float2*>(sWq + k * DD)[lane];
    q0 = fmaf(nk, w.x, q0);
    q1 = fmaf(nk, w.y, q1);
  }
  reinterpret_cast<float2*>(g_queries + i * DD)[lane] = make_float2(q0, q1);
  float2 wp2 = reinterpret_cast<const float2*>(sWp)[lane];
  float rq = q0 * q0 + q1 * q1;
  float rh = n2.x * n2.x + n2.y * n2.y;
  float rp = n2.x * wp2.x + n2.y * wp2.y;
#pragma unroll
  for (int d = 16; d > 0; d >>= 1) {
    rq += __shfl_xor_sync(0xffffffffu, rq, d);
    rh += __shfl_xor_sync(0xffffffffu, rh, d);
    rp += __shfl_xor_sync(0xffffffffu, rp, d);
  }
  if (lane == 0) {
    g_qn[i] = rq;
    g_hn[i] = rh;
    float z = rp + bp[0];
    float prob = 0.5f * tanhf(0.5f * z) + 0.5f;   // XLA logistic
    uint32_t bits = random_bits32(kp0, kp1, (unsigned long long)i);
    float u = u01_from_bits(bits);
    g_gens0[i] = (u < prob * active_nodes[i]) ? 1 : 0;
    g_best[i] = 0ull;
  }
}

// ---------- Kernel B: e_active sum + ordered compaction of generators ----------
__global__ void k_listgen(const float* __restrict__ active_edges) {
  const int tid = threadIdx.x;  // 1024
  const int lane = tid & 31, wid = tid >> 5;
  __shared__ float wsumf[32];
  __shared__ int wsum[32];
  __shared__ int wpre[33];

  const float4* ae4 = reinterpret_cast<const float4*>(active_edges);
  float s = 0.f;
#pragma unroll
  for (int r = 0; r < 4; r++) {
    float4 v = ae4[tid + (r << 10)];
    s += v.x + v.y + v.z + v.w;
  }
#pragma unroll
  for (int d = 16; d > 0; d >>= 1) s += __shfl_xor_sync(0xffffffffu, s, d);
  if (lane == 0) wsumf[wid] = s;

  int flags[8];
  int cnt = 0;
#pragma unroll
  for (int r = 0; r < 8; r++) {
    flags[r] = g_gens0[tid * 8 + r];
    cnt += flags[r];
  }
  int incl = warp_incl_scan(cnt, lane);
  if (lane == 31) wsum[wid] = incl;
  __syncthreads();
  if (wid == 0) {
    int v = wsum[lane];
    int sc = warp_incl_scan(v, lane);
    wpre[lane + 1] = sc;
    if (lane == 0) {
      wpre[0] = 0;
      float t = 0.f;
#pragma unroll
      for (int w = 0; w < 32; w++) t += wsumf[w];
      g_eactive = (int)t;
    }
  }
  __syncthreads();
  int off = wpre[wid] + incl - cnt;
#pragma unroll
  for (int r = 0; r < 8; r++) {
    if (flags[r]) {
      g_glist[off] = tid * 8 + r;
      g_flag[off] = 1;
      off++;
    }
  }
  if (tid == 1023) g_ncand = wpre[32];
}

// ---------- Kernel C: persistent chunk x cand-group scoring ----------
// 256 threads: warps 0-3 handle cands [0,16), warps 4-7 handle [16,32) of the group.
__global__ void __launch_bounds__(SEL_THREADS) k_select(const float* __restrict__ nodes,
                                                        const float* __restrict__ active_nodes,
                                                        uint32_t ks0, uint32_t ks1) {
  __shared__ float sh[TILE_J * TILE_STRIDE];
  __shared__ float qsh[CAND_TILE * DD];
  __shared__ float s_qn[CAND_TILE];
  __shared__ int   s_ii[CAND_TILE];
  const int tid = threadIdx.x;
  const int lane = tid & 31;
  const int jj = tid & 127;
  const int grp2 = tid >> 7;           // 0 or 1
  const int ncand = g_ncand;
  const int ng = (ncand + CAND_TILE - 1) / CAND_TILE;
  const int total = NCHUNK * ng;
  for (int w = blockIdx.x; w < total; w += gridDim.x) {
    const int chunk = w / ng;
    const int grp = w - chunk * ng;
    const int c0 = grp * CAND_TILE;
    const int jbase = chunk << 7;
    // tile load: 8192 floats as 2048 float4, coalesced
    {
      const float4* src = reinterpret_cast<const float4*>(nodes + (jbase << 6));
#pragma unroll
      for (int s = 0; s < 8; s++) {
        int idx4 = (s << 8) + tid;      // 0..2047
        int row = idx4 >> 4, col4 = idx4 & 15;
        reinterpret_cast<float4*>(sh + row * TILE_STRIDE)[col4] = src[idx4];
      }
    }
    // candidate queries / norms
    if (tid < CAND_TILE) {
      int idx = c0 + tid;
      int i = (idx < ncand) ? g_glist[idx] : 0;
      s_ii[tid] = i;
      s_qn[tid] = g_qn[i];
    }
#pragma unroll
    for (int s = 0; s < 2; s++) {
      int t4 = (s << 8) + tid;          // 0..511 -> float4 index into qsh
      int c = t4 >> 4, k4 = t4 & 15;
      int idx = c0 + c;
      float4 qv = (idx < ncand)
          ? reinterpret_cast<const float4*>(g_queries + g_glist[idx] * DD)[k4]
          : make_float4(0.f, 0.f, 0.f, 0.f);
      reinterpret_cast<float4*>(qsh + c * DD)[k4] = qv;
    }
    __syncthreads();
    const int j = jbase + jj;
    const float hn = g_hn[j];
    const float act = active_nodes[j];
    const float4* rowf4 = reinterpret_cast<const float4*>(sh + jj * TILE_STRIDE);
    const int clim = (ncand - c0 < CAND_TILE) ? (ncand - c0) : CAND_TILE;
    const int cbeg = grp2 << 4;
    const int cend = (cbeg + 16 < clim) ? cbeg + 16 : clim;
    for (int c = cbeg; c < cend; c++) {
      const int i = s_ii[c];
      const float4* qf4 = reinterpret_cast<const float4*>(qsh + c * DD);
      float ax = 0.f, ay = 0.f, az = 0.f, aw = 0.f;
#pragma unroll
      for (int kk = 0; kk < 16; kk++) {
        float4 r = rowf4[kk];
        float4 q = qf4[kk];
        ax = fmaf(q.x, r.x, ax);
        ay = fmaf(q.y, r.y, ay);
        az = fmaf(q.z, r.z, az);
        aw = fmaf(q.w, r.w, aw);
      }
      float num = (ax + az) + (ay + aw);
      float sc = num / (sqrtf(s_qn[c] * hn) + 1e-8f);
      sc = fminf(fmaxf(sc, -10000.f), 10000.f);
      if (act <= 0.f) sc = NEGV;
      if (j == i) sc = NEGV;
      unsigned long long lin = (unsigned long long)i * NN + (unsigned long long)j;
      uint32_t bits = random_bits32(ks0, ks1, lin);
      float u = fmaxf(TINYF, u01_from_bits(bits) + TINYF);
      float g = -logf(-logf(u));
      unsigned long long key = enc_key(sc + g, j);
#pragma unroll
      for (int d = 16; d > 0; d >>= 1) {
        unsigned long long o = __shfl_xor_sync(0xffffffffu, key, d);
        if (o > key) key = o;
      }
      if (lane == 0) atomicMax(&g_best[i], key);
    }
    __syncthreads();
  }
}

// ---------- Kernel D: edge-parallel existing-edge check ----------
__global__ void k_exist(const int* __restrict__ senders, const int* __restrict__ receivers) {
  __shared__ unsigned long long keys[2048];
  const int tid = threadIdx.x;  // 256
  const int ncand = g_ncand;
  const int e = (blockIdx.x << 8) + tid;
  const unsigned long long ekey =
      ((unsigned long long)(uint32_t)senders[e] << 32) | (uint32_t)receivers[e];
  for (int base = 0; base < ncand; base += 2048) {
    int m = ncand - base;
    if (m > 2048) m = 2048;
    for (int t = tid; t < m; t += 256) {
      int i = g_glist[base + t];
      unsigned long long b = g_best[i];
      uint32_t sel = 0xFFFFFFFFu - (uint32_t)(b & 0xFFFFFFFFull);
      keys[t] = ((unsigned long long)(uint32_t)i << 32) | sel;
    }
    __syncthreads();
#pragma unroll 4
    for (int k = 0; k < m; k++) {
      if (ekey == keys[k]) g_flag[base + k] = 0;
    }
    __syncthreads();
  }
}

// ---------- Kernel E: final ordered compaction (warp scans) ----------
__global__ void k_compact() {
  const int tid = threadIdx.x;  // 1024
  const int lane = tid & 31, wid = tid >> 5;
  __shared__ int wsum[32];
  __shared__ int wpre[33];
  const int ncand = g_ncand;
  int flags[8];
  int cnt = 0;
#pragma unroll
  for (int r = 0; r < 8; r++) {
    int c = tid * 8 + r;
    flags[r] = (c < ncand) ? g_flag[c] : 0;
    cnt += flags[r];
  }
  int incl = warp_incl_scan(cnt, lane);
  if (lane == 31) wsum[wid] = incl;
  __syncthreads();
  if (wid == 0) {
    int v = wsum[lane];
    int sc = warp_incl_scan(v, lane);
    wpre[lane + 1] = sc;
    if (lane == 0) wpre[0] = 0;
  }
  __syncthreads();
  int off = wpre[wid] + incl - cnt;
#pragma unroll
  for (int r = 0; r < 8; r++) {
    int c = tid * 8 + r;
    if (flags[r]) {
      int i = g_glist[c];
      unsigned long long b = g_best[i];
      g_newsend[off] = i;
      g_newrec[off] = (int)(0xFFFFFFFFu - (uint32_t)(b & 0xFFFFFFFFull));
      off++;
    }
  }
  if (tid == 1023) {
    int total = wpre[32];
    int allowed = EE - g_eactive - 1;
    int n = total < 0 ? 0 : total;
    if (n > allowed) n = allowed;
    g_ngens = n;
  }
}

// ---------- Kernel F: vectorized output writer (MLP=4) ----------
// Layout: [ new_edges (E*D f32) | nsend (E) | nrec (E) | naedges (E) ]
__global__ void k_out4(const float* __restrict__ edges, const int* __restrict__ senders,
                       const int* __restrict__ receivers, float4* __restrict__ out,
                       uint32_t ke0, uint32_t ke1, int n4) {
  const int ngen = g_ngens;
  const int ea = g_eactive;
  const int T1 = EE * DD;
  const int base0 = blockIdx.x * (blockDim.x << 2) + threadIdx.x;
#pragma unroll
  for (int u = 0; u < 4; u++) {
    int idx4 = base0 + u * blockDim.x;
    if (idx4 >= n4) continue;
    int base = idx4 << 2;
    float4 v;
    if (base < T1) {
      v = reinterpret_cast<const float4*>(edges)[idx4];
      int e = base >> 6;
      if (e >= ea && e < ea + ngen) {
        float* vp = reinterpret_cast<float*>(&v);
#pragma unroll
        for (int cmp = 0; cmp < 4; cmp++) {
          uint32_t bits = random_bits32(ke0, ke1, (unsigned long long)(base + cmp));
          float u01 = u01_from_bits(bits);
          const float lo = -0.99999994f;
          float uu = fmaxf(lo, fmaf(u01, 2.0f, lo));
          vp[cmp] += 1.41421356f * xla_erfinv(uu);
        }
      }
    } else if (base < T1 + EE) {
      float* vp = reinterpret_cast<float*>(&v);
#pragma unroll
      for (int cmp = 0; cmp < 4; cmp++) {
        int j = base + cmp - T1;
        float x;
        if (j < ea)             x = (float)senders[j];
        else if (j < ea + ngen) x = (float)g_newsend[j - ea];
        else                    x = (float)(NN - 1);
        vp[cmp] = x;
      }
    } else if (base < T1 + 2 * EE) {
      float* vp = reinterpret_cast<float*>(&v);
#pragma unroll
      for (int cmp = 0; cmp < 4; cmp++) {
        int j = base + cmp - T1 - EE;
        float x;
        if (j < ea)             x = (float)receivers[j];
        else if (j < ea + ngen) x = (float)g_newrec[j - ea];
        else                    x = (float)(NN - 1);
        vp[cmp] = x;
      }
    } else {
      float* vp = reinterpret_cast<float*>(&v);
#pragma unroll
      for (int cmp = 0; cmp < 4; cmp++) {
        int j = base + cmp - T1 - 2 * EE;
        vp[cmp] = (j < ea + ngen) ? 1.0f : 0.0f;
      }
    }
    out[idx4] = v;
  }
}

// fallback scalar writer for non-multiple-of-4 sizes (not expected)
__global__ void k_out1(const float* __restrict__ edges, const int* __restrict__ senders,
                       const int* __restrict__ receivers, float* __restrict__ out,
                       uint32_t ke0, uint32_t ke1, int start, int out_size) {
  int idx = start + blockIdx.x * blockDim.x + threadIdx.x;
  if (idx >= out_size) return;
  const int ngen = g_ngens;
  const int ea = g_eactive;
  const int T1 = EE * DD;
  float x = 0.f;
  if (idx < T1) {
    x = edges[idx];
    int e = idx >> 6;
    if (e >= ea && e < ea + ngen) {
      uint32_t bits = random_bits32(ke0, ke1, (unsigned long long)idx);
      float u01 = u01_from_bits(bits);
      const float lo = -0.99999994f;
      float u = fmaxf(lo, fmaf(u01, 2.0f, lo));
      x += 1.41421356f * xla_erfinv(u);
    }
  } else if (idx < T1 + EE) {
    int j = idx - T1;
    if (j < ea)             x = (float)senders[j];
    else if (j < ea + ngen) x = (float)g_newsend[j - ea];
    else                    x = (float)(NN - 1);
  } else if (idx < T1 + 2 * EE) {
    int j = idx - T1 - EE;
    if (j < ea)             x = (float)receivers[j];
    else if (j < ea + ngen) x = (float)g_newrec[j - ea];
    else                    x = (float)(NN - 1);
  } else if (idx < T1 + 3 * EE) {
    int j = idx - T1 - 2 * EE;
    x = (j < ea + ngen) ? 1.0f : 0.0f;
  }
  out[idx] = x;
}

// ---------------- host ----------------
extern "C" void kernel_launch(void* const* d_in, const int* in_sizes, int n_in,
                              void* d_out, int out_size) {
  const float* nodes        = (const float*)d_in[0];
  const float* edges        = (const float*)d_in[1];
  const int*   receivers    = (const int*)d_in[2];
  const int*   senders      = (const int*)d_in[3];
  const float* active_nodes = (const float*)d_in[4];
  const float* active_edges = (const float*)d_in[5];
  const float* Wq           = (const float*)d_in[6];
  const float* bq           = (const float*)d_in[7];
  const float* Wp           = (const float*)d_in[8];
  const float* bp           = (const float*)d_in[9];
  (void)in_sizes; (void)n_in;

  const uint32_t K0 = 0u, K1 = 42u;
  uint32_t kp0, kp1, ke0, ke1, ks0, ks1;
  threefry2x32(K0, K1, 0u, 0u, &kp0, &kp1);  // key_prob
  threefry2x32(K0, K1, 0u, 1u, &ke0, &ke1);  // key_edges
  threefry2x32(K0, K1, 0u, 2u, &ks0, &ks1);  // key_samp

  k_prep<<<NN / 16, 512>>>(nodes, Wq, bq, Wp, bp, active_nodes, kp0, kp1);
  k_listgen<<<1, 1024>>>(active_edges);
  k_select<<<592, SEL_THREADS>>>(nodes, active_nodes, ks0, ks1);
  k_exist<<<EE / 256, 256>>>(senders, receivers);
  k_compact<<<1, 1024>>>();

  int n4 = out_size >> 2;
  if (n4 > 0) {
    int blocks = (n4 + 1023) / 1024;
    k_out4<<<blocks, 256>>>(edges, senders, receivers, (float4*)d_out, ke0, ke1, n4);
  }
  int rem_start = n4 << 2;
  if (rem_start < out_size)
    k_out1<<<1, 256>>>(edges, senders, receivers, (float*)d_out, ke0, ke1,
                       rem_start, out_size);
}